// round 10
// baseline (speedup 1.0000x reference)
#include <cuda_runtime.h>
#include <cuda_bf16.h>
#include <cstdint>

#define N_NODES 100000
#define NFEAT   256
#define NHID    256
#define NCLASS  64
#define KDIM    256

// ---------------- scratch (device globals; no runtime allocation) ----------------
__device__ __align__(128) float         g_S[(size_t)N_NODES * NHID];     // fp32 GEMM out / SpMM in
__device__ __align__(128) __nv_bfloat16 g_xh[(size_t)N_NODES * NFEAT];
__device__ __align__(128) __nv_bfloat16 g_xl[(size_t)N_NODES * NFEAT];
__device__ __align__(128) __nv_bfloat16 g_hh[(size_t)N_NODES * NHID];
__device__ __align__(128) __nv_bfloat16 g_hl[(size_t)N_NODES * NHID];
__device__ __align__(128) __nv_bfloat16 g_w1t_h[KDIM * NHID], g_w1t_l[KDIM * NHID]; // W1^T [N,K]
__device__ __align__(128) __nv_bfloat16 g_w2t_h[KDIM * NHID], g_w2t_l[KDIM * NHID]; // W2^T
__device__ __align__(128) __nv_bfloat16 g_wht_h[128 * KDIM],  g_wht_l[128 * KDIM];  // [WL1|WL2]^T
__device__ float g_headb[2 * NCLASS];
__device__ int   g_row_ptr[N_NODES + 1];

// ---------------- small PTX helpers ----------------
__device__ __forceinline__ void cp16(uint32_t s, const __nv_bfloat16* g, bool v) {
    int sz = v ? 16 : 0;
    asm volatile("cp.async.cg.shared.global [%0], [%1], 16, %2;"
                 :: "r"(s), "l"(__cvta_generic_to_global(g)), "r"(sz));
}
#define CP_COMMIT() asm volatile("cp.async.commit_group;" ::: "memory")

__device__ __forceinline__ void ldsm4(uint32_t* r, uint32_t a) {
    asm volatile("ldmatrix.sync.aligned.m8n8.x4.shared.b16 {%0,%1,%2,%3}, [%4];"
                 : "=r"(r[0]), "=r"(r[1]), "=r"(r[2]), "=r"(r[3]) : "r"(a));
}
__device__ __forceinline__ void mma16816(float* c, const uint32_t* a, const uint32_t* b) {
    asm volatile("mma.sync.aligned.m16n8k16.row.col.f32.bf16.bf16.f32 "
                 "{%0,%1,%2,%3}, {%4,%5,%6,%7}, {%8,%9}, {%0,%1,%2,%3};"
                 : "+f"(c[0]), "+f"(c[1]), "+f"(c[2]), "+f"(c[3])
                 : "r"(a[0]), "r"(a[1]), "r"(a[2]), "r"(a[3]), "r"(b[0]), "r"(b[1]));
}

// ---------------- CSR row_ptr from sorted edge_dst ----------------
__global__ void build_row_ptr_kernel(const int* __restrict__ dst, int n_edges) {
    int i = blockIdx.x * blockDim.x + threadIdx.x;
    if (i > N_NODES) return;
    int lo = 0, hi = n_edges;
    while (lo < hi) {
        int mid = (lo + hi) >> 1;
        if (dst[mid] < i) lo = mid + 1; else hi = mid;
    }
    g_row_ptr[i] = lo;
}

// ---------------- weight prep: transpose + bf16 split ----------------
__device__ __forceinline__ void split_store(__nv_bfloat16* ph, __nv_bfloat16* pl, float v) {
    __nv_bfloat16 hi = __float2bfloat16(v);
    *ph = hi;
    *pl = __float2bfloat16(v - __bfloat162float(hi));
}
__global__ void prep_w_kernel(const float* __restrict__ W1, const float* __restrict__ W2,
                              const float* __restrict__ WL1, const float* __restrict__ WL2,
                              const float* __restrict__ bL1, const float* __restrict__ bL2) {
    int i = blockIdx.x * blockDim.x + threadIdx.x;
    if (i < KDIM * NHID) {
        int n = i >> 8, k = i & 255;
        split_store(&g_w1t_h[i], &g_w1t_l[i], W1[k * NHID + n]);
        split_store(&g_w2t_h[i], &g_w2t_l[i], W2[k * NHID + n]);
    }
    if (i < 128 * KDIM) {
        int n = i >> 8, k = i & 255;
        float v = (n < NCLASS) ? WL1[k * NCLASS + n] : WL2[k * NCLASS + (n - NCLASS)];
        split_store(&g_wht_h[i], &g_wht_l[i], v);
    }
    if (i < 2 * NCLASS)
        g_headb[i] = (i < NCLASS) ? bL1[i] : bL2[i - NCLASS];
}

// ---------------- x -> bf16 hi/lo ----------------
__global__ void convert_x_kernel(const float* __restrict__ x) {
    int i = blockIdx.x * blockDim.x + threadIdx.x;
    if (i >= N_NODES * NFEAT) return;
    split_store(&g_xh[i], &g_xl[i], x[i]);
}

// ---------------- mma.sync split-bf16 GEMM (CTA 128x128, term-major MMA order) ----------------
// C = (Ah+Al) @ (Bh+Bl)^T via AhBh + AhBl + AlBh, fp32 accum.
// A: [M,256] bf16 row-major; B: [Nrows,256] bf16 row-major (= W^T, K-major).
// K-chunk 64, 3-stage cp.async pipeline (1 sync/iter); warps 2(M) x 4(N), warp tile 64x32.
// MMAs issued term-major within each k16 so same-acc MMAs are 16 apart (no RAW chains).
constexpr int KC     = 64;
constexpr int ROWB   = 144;            // (64+8) halves * 2B, 16B aligned, ldsm conflict-free
constexpr int TILEB  = 128 * ROWB;     // 18432
constexpr int STAGEB = 4 * TILEB;      // 73728  (tiles: Ah, Al, Bh, Bl)
constexpr int GEMM_SMEM = 3 * STAGEB;  // 221184 (fits 227KB)

template <bool HEAD>
__global__ void __launch_bounds__(256, 1) gemm_mma_kernel(
    const __nv_bfloat16* __restrict__ Ah, const __nv_bfloat16* __restrict__ Al,
    const __nv_bfloat16* __restrict__ Bh, const __nv_bfloat16* __restrict__ Bl,
    float* __restrict__ out, int M, int ldC)
{
    extern __shared__ __align__(128) char smem[];
    const int tid = threadIdx.x, lane = tid & 31, wid = tid >> 5;
    const int wm = wid >> 2, wn = wid & 3;            // 2(M) x 4(N) warps, warp tile 64x32
    const int m0 = blockIdx.y * 128;
    const int n0 = blockIdx.x * 128;
    const __nv_bfloat16* BhO = Bh + (size_t)n0 * KDIM;
    const __nv_bfloat16* BlO = Bl + (size_t)n0 * KDIM;
    uint32_t sb = (uint32_t)__cvta_generic_to_shared(smem);

    float acc[4][4][4];
#pragma unroll
    for (int a = 0; a < 4; a++)
#pragma unroll
        for (int b = 0; b < 4; b++)
#pragma unroll
            for (int c = 0; c < 4; c++) acc[a][b][c] = 0.f;

    auto load_stage = [&](int stage, int kc) {
        uint32_t base = sb + stage * STAGEB;
        for (int i = tid; i < 4096; i += 256) {
            int t = i >> 10, rc = i & 1023, r = rc >> 3, ch = rc & 7;
            const __nv_bfloat16* src;
            bool v = true;
            if (t == 0)      { src = Ah  + (size_t)(m0 + r) * KDIM + kc + ch * 8; v = (m0 + r) < M; }
            else if (t == 1) { src = Al  + (size_t)(m0 + r) * KDIM + kc + ch * 8; v = (m0 + r) < M; }
            else if (t == 2) { src = BhO + (size_t)r * KDIM + kc + ch * 8; }
            else             { src = BlO + (size_t)r * KDIM + kc + ch * 8; }
            cp16(base + t * TILEB + r * ROWB + ch * 16, src, v);
        }
    };

    const int ar  = lane & 15;
    const int acx = ((lane >> 4) & 1) * 8;
    const int br  = ((lane >> 4) << 3) + (lane & 7);
    const int bc  = ((lane >> 3) & 1) * 8;

    auto compute = [&](int stage) {
        uint32_t aH = sb + stage * STAGEB;
        uint32_t aL = aH + TILEB;
        uint32_t bH = aH + 2 * TILEB;
        uint32_t bL = aH + 3 * TILEB;
#pragma unroll
        for (int k16 = 0; k16 < KC / 16; k16++) {
            uint32_t ah[4][4], al[4][4], bh[4][2], bl[4][2];
#pragma unroll
            for (int mf = 0; mf < 4; mf++) {
                uint32_t off = (uint32_t)((wm * 64 + mf * 16 + ar) * ROWB + (acx + k16 * 16) * 2);
                ldsm4(ah[mf], aH + off);
                ldsm4(al[mf], aL + off);
            }
#pragma unroll
            for (int np = 0; np < 2; np++) {
                uint32_t off = (uint32_t)((wn * 32 + np * 16 + br) * ROWB + (bc + k16 * 16) * 2);
                uint32_t t[4];
                ldsm4(t, bH + off);
                bh[np*2][0] = t[0]; bh[np*2][1] = t[1]; bh[np*2+1][0] = t[2]; bh[np*2+1][1] = t[3];
                ldsm4(t, bL + off);
                bl[np*2][0] = t[0]; bl[np*2][1] = t[1]; bl[np*2+1][0] = t[2]; bl[np*2+1][1] = t[3];
            }
            // term-major: 16 independent accs between reuses of the same acc
#pragma unroll
            for (int mf = 0; mf < 4; mf++)
#pragma unroll
                for (int nf = 0; nf < 4; nf++)
                    mma16816(acc[mf][nf], ah[mf], bh[nf]);
#pragma unroll
            for (int mf = 0; mf < 4; mf++)
#pragma unroll
                for (int nf = 0; nf < 4; nf++)
                    mma16816(acc[mf][nf], ah[mf], bl[nf]);
#pragma unroll
            for (int mf = 0; mf < 4; mf++)
#pragma unroll
                for (int nf = 0; nf < 4; nf++)
                    mma16816(acc[mf][nf], al[mf], bh[nf]);
        }
    };

    constexpr int NIT = KDIM / KC;   // 4
    load_stage(0, 0);       CP_COMMIT();
    load_stage(1, KC);      CP_COMMIT();
#pragma unroll
    for (int it = 0; it < NIT; it++) {
        if (it + 1 < NIT) { asm volatile("cp.async.wait_group 1;" ::: "memory"); }
        else              { asm volatile("cp.async.wait_group 0;" ::: "memory"); }
        __syncthreads();
        compute(it % 3);
        if (it + 2 < NIT) { load_stage((it + 2) % 3, (it + 2) * KC); CP_COMMIT(); }
    }

    // ---- epilogue ----
#pragma unroll
    for (int mf = 0; mf < 4; mf++) {
        int rbase = m0 + wm * 64 + mf * 16 + (lane >> 2);
#pragma unroll
        for (int nf = 0; nf < 4; nf++) {
            int col = (HEAD ? 0 : n0) + wn * 32 + nf * 8 + (lane & 3) * 2;
#pragma unroll
            for (int h = 0; h < 2; h++) {
                int row = rbase + h * 8;
                if (row >= M) continue;
                float2 v = make_float2(acc[mf][nf][h * 2], acc[mf][nf][h * 2 + 1]);
                if (!HEAD) {
                    *(float2*)(out + (size_t)row * ldC + col) = v;
                } else {
                    v.x += g_headb[col]; v.y += g_headb[col + 1];
                    float* dst = (col < NCLASS)
                        ? out + (size_t)row * NCLASS + col
                        : out + (size_t)N_NODES * NCLASS + (size_t)row * NCLASS + (col - NCLASS);
                    *(float2*)dst = v;
                }
            }
        }
    }
}

// ---------------- SpMM half-pass + bias + relu -> bf16 hi/lo split ----------------
// Processes 128 feature columns per pass (working set 51MB -> L2-resident).
struct __align__(8) bf16x4 { __nv_bfloat162 a, b; };
__device__ __forceinline__ void emit4(__nv_bfloat16* Hh, __nv_bfloat16* Hl, size_t idx,
                                      float4 acc, float4 bia) {
    float v0 = fmaxf(acc.x + bia.x, 0.f), v1 = fmaxf(acc.y + bia.y, 0.f);
    float v2 = fmaxf(acc.z + bia.z, 0.f), v3 = fmaxf(acc.w + bia.w, 0.f);
    __nv_bfloat16 h0 = __float2bfloat16(v0), h1 = __float2bfloat16(v1);
    __nv_bfloat16 h2 = __float2bfloat16(v2), h3 = __float2bfloat16(v3);
    bf16x4 hv; hv.a = __nv_bfloat162(h0, h1); hv.b = __nv_bfloat162(h2, h3);
    *(bf16x4*)(Hh + idx) = hv;
    bf16x4 lv;
    lv.a = __nv_bfloat162(__float2bfloat16(v0 - __bfloat162float(h0)),
                          __float2bfloat16(v1 - __bfloat162float(h1)));
    lv.b = __nv_bfloat162(__float2bfloat16(v2 - __bfloat162float(h2)),
                          __float2bfloat16(v3 - __bfloat162float(h3)));
    *(bf16x4*)(Hl + idx) = lv;
}

__device__ __forceinline__ void fma4(float4& acc, float s, const float4& v) {
    acc.x += s * v.x; acc.y += s * v.y; acc.z += s * v.z; acc.w += s * v.w;
}

__global__ void __launch_bounds__(256) spmm_half_kernel(
    const float* __restrict__ S, const int* __restrict__ src,
    const float* __restrict__ w, const float* __restrict__ bias,
    __nv_bfloat16* __restrict__ Hh, __nv_bfloat16* __restrict__ Hl, int colOff)
{
    int node = (blockIdx.x * blockDim.x + threadIdx.x) >> 5;
    if (node >= N_NODES) return;
    int lane = threadIdx.x & 31;
    int e0 = g_row_ptr[node], e1 = g_row_ptr[node + 1];
    const float* Sc = S + colOff + lane * 4;

    float4 acc = make_float4(0.f, 0.f, 0.f, 0.f);
    int e = e0;
    for (; e + 4 <= e1; e += 4) {
        int   s0 = __ldg(src + e),     s1 = __ldg(src + e + 1);
        int   s2 = __ldg(src + e + 2), s3 = __ldg(src + e + 3);
        float w0 = __ldg(w + e),     w1 = __ldg(w + e + 1);
        float w2 = __ldg(w + e + 2), w3 = __ldg(w + e + 3);
        float4 a0 = __ldg((const float4*)(Sc + (size_t)s0 * NHID));
        float4 a1 = __ldg((const float4*)(Sc + (size_t)s1 * NHID));
        float4 a2 = __ldg((const float4*)(Sc + (size_t)s2 * NHID));
        float4 a3 = __ldg((const float4*)(Sc + (size_t)s3 * NHID));
        fma4(acc, w0, a0); fma4(acc, w1, a1); fma4(acc, w2, a2); fma4(acc, w3, a3);
    }
    for (; e < e1; e++) {
        int   s  = __ldg(src + e);
        float sw = __ldg(w + e);
        float4 a = __ldg((const float4*)(Sc + (size_t)s * NHID));
        fma4(acc, sw, a);
    }

    float4 bia = *(const float4*)(bias + colOff + lane * 4);
    emit4(Hh, Hl, (size_t)node * NHID + colOff + lane * 4, acc, bia);
}

// ---------------- launch ----------------
extern "C" void kernel_launch(void* const* d_in, const int* in_sizes, int n_in,
                              void* d_out, int out_size) {
    const float* x   = (const float*)d_in[0];
    const int*   es  = (const int*)  d_in[1];
    const int*   ed  = (const int*)  d_in[2];
    const float* ew  = (const float*)d_in[3];
    const float* W1  = (const float*)d_in[4];
    const float* b1  = (const float*)d_in[5];
    const float* W2  = (const float*)d_in[6];
    const float* b2  = (const float*)d_in[7];
    const float* WL1 = (const float*)d_in[8];
    const float* bL1 = (const float*)d_in[9];
    const float* WL2 = (const float*)d_in[10];
    const float* bL2 = (const float*)d_in[11];
    int n_edges = in_sizes[1];

    float *S; __nv_bfloat16 *xh, *xl, *hh, *hl, *w1h, *w1l, *w2h, *w2l, *whh, *whl;
    cudaGetSymbolAddress((void**)&S,   g_S);
    cudaGetSymbolAddress((void**)&xh,  g_xh);    cudaGetSymbolAddress((void**)&xl,  g_xl);
    cudaGetSymbolAddress((void**)&hh,  g_hh);    cudaGetSymbolAddress((void**)&hl,  g_hl);
    cudaGetSymbolAddress((void**)&w1h, g_w1t_h); cudaGetSymbolAddress((void**)&w1l, g_w1t_l);
    cudaGetSymbolAddress((void**)&w2h, g_w2t_h); cudaGetSymbolAddress((void**)&w2l, g_w2t_l);
    cudaGetSymbolAddress((void**)&whh, g_wht_h); cudaGetSymbolAddress((void**)&whl, g_wht_l);

    cudaFuncSetAttribute(gemm_mma_kernel<false>,
                         cudaFuncAttributeMaxDynamicSharedMemorySize, GEMM_SMEM);
    cudaFuncSetAttribute(gemm_mma_kernel<true>,
                         cudaFuncAttributeMaxDynamicSharedMemorySize, GEMM_SMEM);

    const int MTILES = (N_NODES + 127) / 128;   // 782
    const int spmm_blocks = (N_NODES + 7) / 8;  // 8 warps/block

    build_row_ptr_kernel<<<(N_NODES + 256) / 256, 256>>>(ed, n_edges);
    prep_w_kernel<<<(KDIM * NHID + 255) / 256, 256>>>(W1, W2, WL1, WL2, bL1, bL2);
    convert_x_kernel<<<(N_NODES * NFEAT + 255) / 256, 256>>>(x);

    // layer 1
    gemm_mma_kernel<false><<<dim3(2, MTILES), 256, GEMM_SMEM>>>(xh, xl, w1h, w1l, S, N_NODES, NHID);
    spmm_half_kernel<<<spmm_blocks, 256>>>(S, es, ew, b1, hh, hl, 0);
    spmm_half_kernel<<<spmm_blocks, 256>>>(S, es, ew, b1, hh, hl, 128);
    // layer 2
    gemm_mma_kernel<false><<<dim3(2, MTILES), 256, GEMM_SMEM>>>(hh, hl, w2h, w2l, S, N_NODES, NHID);
    spmm_half_kernel<<<spmm_blocks, 256>>>(S, es, ew, b2, hh, hl, 0);
    spmm_half_kernel<<<spmm_blocks, 256>>>(S, es, ew, b2, hh, hl, 128);
    // twin heads
    gemm_mma_kernel<true><<<dim3(1, MTILES), 256, GEMM_SMEM>>>(hh, hl, whh, whl, (float*)d_out, N_NODES, 128);
}

// round 11
// speedup vs baseline: 1.5622x; 1.5622x over previous
#include <cuda_runtime.h>
#include <cuda_bf16.h>
#include <cstdint>

#define N_NODES 100000
#define NFEAT   256
#define NHID    256
#define NCLASS  64
#define KDIM    256

// ---------------- scratch (device globals; no runtime allocation) ----------------
__device__ __align__(128) float         g_S[(size_t)N_NODES * NHID];     // fp32 GEMM out / SpMM in
__device__ __align__(128) __nv_bfloat16 g_xh[(size_t)N_NODES * NFEAT];
__device__ __align__(128) __nv_bfloat16 g_xl[(size_t)N_NODES * NFEAT];
__device__ __align__(128) __nv_bfloat16 g_hh[(size_t)N_NODES * NHID];
__device__ __align__(128) __nv_bfloat16 g_hl[(size_t)N_NODES * NHID];
__device__ __align__(128) __nv_bfloat16 g_w1t_h[KDIM * NHID], g_w1t_l[KDIM * NHID]; // W1^T [N,K]
__device__ __align__(128) __nv_bfloat16 g_w2t_h[KDIM * NHID], g_w2t_l[KDIM * NHID]; // W2^T
__device__ __align__(128) __nv_bfloat16 g_wht_h[128 * KDIM],  g_wht_l[128 * KDIM];  // [WL1|WL2]^T
__device__ float g_headb[2 * NCLASS];
__device__ int   g_row_ptr[N_NODES + 1];

// ---------------- small PTX helpers ----------------
__device__ __forceinline__ void cp16(uint32_t s, const __nv_bfloat16* g, bool v) {
    int sz = v ? 16 : 0;
    asm volatile("cp.async.cg.shared.global [%0], [%1], 16, %2;"
                 :: "r"(s), "l"(__cvta_generic_to_global(g)), "r"(sz));
}
#define CP_COMMIT() asm volatile("cp.async.commit_group;" ::: "memory")

__device__ __forceinline__ void ldsm4(uint32_t* r, uint32_t a) {
    asm volatile("ldmatrix.sync.aligned.m8n8.x4.shared.b16 {%0,%1,%2,%3}, [%4];"
                 : "=r"(r[0]), "=r"(r[1]), "=r"(r[2]), "=r"(r[3]) : "r"(a));
}
__device__ __forceinline__ void mma16816(float* c, const uint32_t* a, const uint32_t* b) {
    asm volatile("mma.sync.aligned.m16n8k16.row.col.f32.bf16.bf16.f32 "
                 "{%0,%1,%2,%3}, {%4,%5,%6,%7}, {%8,%9}, {%0,%1,%2,%3};"
                 : "+f"(c[0]), "+f"(c[1]), "+f"(c[2]), "+f"(c[3])
                 : "r"(a[0]), "r"(a[1]), "r"(a[2]), "r"(a[3]), "r"(b[0]), "r"(b[1]));
}

// ---------------- CSR row_ptr from sorted edge_dst ----------------
__global__ void build_row_ptr_kernel(const int* __restrict__ dst, int n_edges) {
    int i = blockIdx.x * blockDim.x + threadIdx.x;
    if (i > N_NODES) return;
    int lo = 0, hi = n_edges;
    while (lo < hi) {
        int mid = (lo + hi) >> 1;
        if (dst[mid] < i) lo = mid + 1; else hi = mid;
    }
    g_row_ptr[i] = lo;
}

// ---------------- weight prep: transpose + bf16 split ----------------
__device__ __forceinline__ void split_store(__nv_bfloat16* ph, __nv_bfloat16* pl, float v) {
    __nv_bfloat16 hi = __float2bfloat16(v);
    *ph = hi;
    *pl = __float2bfloat16(v - __bfloat162float(hi));
}
__global__ void prep_w_kernel(const float* __restrict__ W1, const float* __restrict__ W2,
                              const float* __restrict__ WL1, const float* __restrict__ WL2,
                              const float* __restrict__ bL1, const float* __restrict__ bL2) {
    int i = blockIdx.x * blockDim.x + threadIdx.x;
    if (i < KDIM * NHID) {
        int n = i >> 8, k = i & 255;
        split_store(&g_w1t_h[i], &g_w1t_l[i], W1[k * NHID + n]);
        split_store(&g_w2t_h[i], &g_w2t_l[i], W2[k * NHID + n]);
    }
    if (i < 128 * KDIM) {
        int n = i >> 8, k = i & 255;
        float v = (n < NCLASS) ? WL1[k * NCLASS + n] : WL2[k * NCLASS + (n - NCLASS)];
        split_store(&g_wht_h[i], &g_wht_l[i], v);
    }
    if (i < 2 * NCLASS)
        g_headb[i] = (i < NCLASS) ? bL1[i] : bL2[i - NCLASS];
}

// ---------------- x -> bf16 hi/lo ----------------
__global__ void convert_x_kernel(const float* __restrict__ x) {
    int i = blockIdx.x * blockDim.x + threadIdx.x;
    if (i >= N_NODES * NFEAT) return;
    split_store(&g_xh[i], &g_xl[i], x[i]);
}

// ---------------- mma.sync split-bf16 GEMM (CTA 128x128, KC=32, 2 CTA/SM) ----------------
// C = (Ah+Al) @ (Bh+Bl)^T via AhBh + AhBl + AlBh, fp32 accum.
// A: [M,256] bf16 row-major; B: [Nrows,256] bf16 row-major (= W^T, K-major).
// K-chunk 32, 2-stage cp.async pipeline; warps 2(M) x 4(N), warp tile 64x32.
// Stage = 40KB -> 2 stages = 80KB -> 2 CTAs/SM resident (phase interleave).
constexpr int KC     = 32;
constexpr int ROWB   = 80;             // (32+8) halves * 2B; gcd(80,128)=16 -> 8 rows conflict-free
constexpr int TILEB  = 128 * ROWB;     // 10240
constexpr int STAGEB = 4 * TILEB;      // 40960  (tiles: Ah, Al, Bh, Bl)
constexpr int GEMM_SMEM = 2 * STAGEB;  // 81920  (2 CTAs/SM fit in 228KB)

template <bool HEAD>
__global__ void __launch_bounds__(256, 2) gemm_mma_kernel(
    const __nv_bfloat16* __restrict__ Ah, const __nv_bfloat16* __restrict__ Al,
    const __nv_bfloat16* __restrict__ Bh, const __nv_bfloat16* __restrict__ Bl,
    float* __restrict__ out, int M, int ldC)
{
    extern __shared__ __align__(128) char smem[];
    const int tid = threadIdx.x, lane = tid & 31, wid = tid >> 5;
    const int wm = wid >> 2, wn = wid & 3;            // 2(M) x 4(N) warps, warp tile 64x32
    const int m0 = blockIdx.y * 128;
    const int n0 = blockIdx.x * 128;
    const __nv_bfloat16* BhO = Bh + (size_t)n0 * KDIM;
    const __nv_bfloat16* BlO = Bl + (size_t)n0 * KDIM;
    uint32_t sb = (uint32_t)__cvta_generic_to_shared(smem);

    float acc[4][4][4];
#pragma unroll
    for (int a = 0; a < 4; a++)
#pragma unroll
        for (int b = 0; b < 4; b++)
#pragma unroll
            for (int c = 0; c < 4; c++) acc[a][b][c] = 0.f;

    // stage loader: 4 tiles x 128 rows x 4 chunks(16B) = 2048 cp.async
    auto load_stage = [&](int stage, int kc) {
        uint32_t base = sb + stage * STAGEB;
        for (int i = tid; i < 2048; i += 256) {
            int t = i >> 9, rc = i & 511, r = rc >> 2, ch = rc & 3;
            const __nv_bfloat16* src;
            bool v = true;
            if (t == 0)      { src = Ah  + (size_t)(m0 + r) * KDIM + kc + ch * 8; v = (m0 + r) < M; }
            else if (t == 1) { src = Al  + (size_t)(m0 + r) * KDIM + kc + ch * 8; v = (m0 + r) < M; }
            else if (t == 2) { src = BhO + (size_t)r * KDIM + kc + ch * 8; }
            else             { src = BlO + (size_t)r * KDIM + kc + ch * 8; }
            cp16(base + t * TILEB + r * ROWB + ch * 16, src, v);
        }
    };

    const int ar  = lane & 15;
    const int acx = ((lane >> 4) & 1) * 8;
    const int br  = ((lane >> 4) << 3) + (lane & 7);
    const int bc  = ((lane >> 3) & 1) * 8;

    auto compute = [&](int stage) {
        uint32_t aH = sb + stage * STAGEB;
        uint32_t aL = aH + TILEB;
        uint32_t bH = aH + 2 * TILEB;
        uint32_t bL = aH + 3 * TILEB;
#pragma unroll
        for (int k16 = 0; k16 < KC / 16; k16++) {
            uint32_t ah[4][4], al[4][4], bh[4][2], bl[4][2];
#pragma unroll
            for (int mf = 0; mf < 4; mf++) {
                uint32_t off = (uint32_t)((wm * 64 + mf * 16 + ar) * ROWB + (acx + k16 * 16) * 2);
                ldsm4(ah[mf], aH + off);
                ldsm4(al[mf], aL + off);
            }
#pragma unroll
            for (int np = 0; np < 2; np++) {
                uint32_t off = (uint32_t)((wn * 32 + np * 16 + br) * ROWB + (bc + k16 * 16) * 2);
                uint32_t t[4];
                ldsm4(t, bH + off);
                bh[np*2][0] = t[0]; bh[np*2][1] = t[1]; bh[np*2+1][0] = t[2]; bh[np*2+1][1] = t[3];
                ldsm4(t, bL + off);
                bl[np*2][0] = t[0]; bl[np*2][1] = t[1]; bl[np*2+1][0] = t[2]; bl[np*2+1][1] = t[3];
            }
#pragma unroll
            for (int mf = 0; mf < 4; mf++)
#pragma unroll
                for (int nf = 0; nf < 4; nf++) {
                    mma16816(acc[mf][nf], ah[mf], bh[nf]);
                    mma16816(acc[mf][nf], ah[mf], bl[nf]);
                    mma16816(acc[mf][nf], al[mf], bh[nf]);
                }
        }
    };

    constexpr int NIT = KDIM / KC;   // 8
    load_stage(0, 0);
    CP_COMMIT();
#pragma unroll
    for (int it = 0; it < NIT; it++) {
        if (it + 1 < NIT) {
            load_stage((it + 1) & 1, (it + 1) * KC);
            CP_COMMIT();
            asm volatile("cp.async.wait_group 1;" ::: "memory");
        } else {
            asm volatile("cp.async.wait_group 0;" ::: "memory");
        }
        __syncthreads();
        compute(it & 1);
        __syncthreads();
    }

    // ---- epilogue ----
#pragma unroll
    for (int mf = 0; mf < 4; mf++) {
        int rbase = m0 + wm * 64 + mf * 16 + (lane >> 2);
#pragma unroll
        for (int nf = 0; nf < 4; nf++) {
            int col = (HEAD ? 0 : n0) + wn * 32 + nf * 8 + (lane & 3) * 2;
#pragma unroll
            for (int h = 0; h < 2; h++) {
                int row = rbase + h * 8;
                if (row >= M) continue;
                float2 v = make_float2(acc[mf][nf][h * 2], acc[mf][nf][h * 2 + 1]);
                if (!HEAD) {
                    *(float2*)(out + (size_t)row * ldC + col) = v;
                } else {
                    v.x += g_headb[col]; v.y += g_headb[col + 1];
                    float* dst = (col < NCLASS)
                        ? out + (size_t)row * NCLASS + col
                        : out + (size_t)N_NODES * NCLASS + (size_t)row * NCLASS + (col - NCLASS);
                    *(float2*)dst = v;
                }
            }
        }
    }
}

// ---------------- SpMM half-pass + bias + relu -> bf16 hi/lo split ----------------
// Processes 128 feature columns per pass (working set 51MB -> L2-resident).
struct __align__(8) bf16x4 { __nv_bfloat162 a, b; };
__device__ __forceinline__ void emit4(__nv_bfloat16* Hh, __nv_bfloat16* Hl, size_t idx,
                                      float4 acc, float4 bia) {
    float v0 = fmaxf(acc.x + bia.x, 0.f), v1 = fmaxf(acc.y + bia.y, 0.f);
    float v2 = fmaxf(acc.z + bia.z, 0.f), v3 = fmaxf(acc.w + bia.w, 0.f);
    __nv_bfloat16 h0 = __float2bfloat16(v0), h1 = __float2bfloat16(v1);
    __nv_bfloat16 h2 = __float2bfloat16(v2), h3 = __float2bfloat16(v3);
    bf16x4 hv; hv.a = __nv_bfloat162(h0, h1); hv.b = __nv_bfloat162(h2, h3);
    *(bf16x4*)(Hh + idx) = hv;
    bf16x4 lv;
    lv.a = __nv_bfloat162(__float2bfloat16(v0 - __bfloat162float(h0)),
                          __float2bfloat16(v1 - __bfloat162float(h1)));
    lv.b = __nv_bfloat162(__float2bfloat16(v2 - __bfloat162float(h2)),
                          __float2bfloat16(v3 - __bfloat162float(h3)));
    *(bf16x4*)(Hl + idx) = lv;
}

__device__ __forceinline__ void fma4(float4& acc, float s, const float4& v) {
    acc.x += s * v.x; acc.y += s * v.y; acc.z += s * v.z; acc.w += s * v.w;
}

__global__ void __launch_bounds__(256) spmm_half_kernel(
    const float* __restrict__ S, const int* __restrict__ src,
    const float* __restrict__ w, const float* __restrict__ bias,
    __nv_bfloat16* __restrict__ Hh, __nv_bfloat16* __restrict__ Hl, int colOff)
{
    int node = (blockIdx.x * blockDim.x + threadIdx.x) >> 5;
    if (node >= N_NODES) return;
    int lane = threadIdx.x & 31;
    int e0 = g_row_ptr[node], e1 = g_row_ptr[node + 1];
    const float* Sc = S + colOff + lane * 4;

    float4 acc = make_float4(0.f, 0.f, 0.f, 0.f);
    int e = e0;
    for (; e + 4 <= e1; e += 4) {
        int   s0 = __ldg(src + e),     s1 = __ldg(src + e + 1);
        int   s2 = __ldg(src + e + 2), s3 = __ldg(src + e + 3);
        float w0 = __ldg(w + e),     w1 = __ldg(w + e + 1);
        float w2 = __ldg(w + e + 2), w3 = __ldg(w + e + 3);
        float4 a0 = __ldg((const float4*)(Sc + (size_t)s0 * NHID));
        float4 a1 = __ldg((const float4*)(Sc + (size_t)s1 * NHID));
        float4 a2 = __ldg((const float4*)(Sc + (size_t)s2 * NHID));
        float4 a3 = __ldg((const float4*)(Sc + (size_t)s3 * NHID));
        fma4(acc, w0, a0); fma4(acc, w1, a1); fma4(acc, w2, a2); fma4(acc, w3, a3);
    }
    for (; e < e1; e++) {
        int   s  = __ldg(src + e);
        float sw = __ldg(w + e);
        float4 a = __ldg((const float4*)(Sc + (size_t)s * NHID));
        fma4(acc, sw, a);
    }

    float4 bia = *(const float4*)(bias + colOff + lane * 4);
    emit4(Hh, Hl, (size_t)node * NHID + colOff + lane * 4, acc, bia);
}

// ---------------- launch ----------------
extern "C" void kernel_launch(void* const* d_in, const int* in_sizes, int n_in,
                              void* d_out, int out_size) {
    const float* x   = (const float*)d_in[0];
    const int*   es  = (const int*)  d_in[1];
    const int*   ed  = (const int*)  d_in[2];
    const float* ew  = (const float*)d_in[3];
    const float* W1  = (const float*)d_in[4];
    const float* b1  = (const float*)d_in[5];
    const float* W2  = (const float*)d_in[6];
    const float* b2  = (const float*)d_in[7];
    const float* WL1 = (const float*)d_in[8];
    const float* bL1 = (const float*)d_in[9];
    const float* WL2 = (const float*)d_in[10];
    const float* bL2 = (const float*)d_in[11];
    int n_edges = in_sizes[1];

    float *S; __nv_bfloat16 *xh, *xl, *hh, *hl, *w1h, *w1l, *w2h, *w2l, *whh, *whl;
    cudaGetSymbolAddress((void**)&S,   g_S);
    cudaGetSymbolAddress((void**)&xh,  g_xh);    cudaGetSymbolAddress((void**)&xl,  g_xl);
    cudaGetSymbolAddress((void**)&hh,  g_hh);    cudaGetSymbolAddress((void**)&hl,  g_hl);
    cudaGetSymbolAddress((void**)&w1h, g_w1t_h); cudaGetSymbolAddress((void**)&w1l, g_w1t_l);
    cudaGetSymbolAddress((void**)&w2h, g_w2t_h); cudaGetSymbolAddress((void**)&w2l, g_w2t_l);
    cudaGetSymbolAddress((void**)&whh, g_wht_h); cudaGetSymbolAddress((void**)&whl, g_wht_l);

    cudaFuncSetAttribute(gemm_mma_kernel<false>,
                         cudaFuncAttributeMaxDynamicSharedMemorySize, GEMM_SMEM);
    cudaFuncSetAttribute(gemm_mma_kernel<true>,
                         cudaFuncAttributeMaxDynamicSharedMemorySize, GEMM_SMEM);

    const int MTILES = (N_NODES + 127) / 128;   // 782
    const int spmm_blocks = (N_NODES + 7) / 8;  // 8 warps/block

    build_row_ptr_kernel<<<(N_NODES + 256) / 256, 256>>>(ed, n_edges);
    prep_w_kernel<<<(KDIM * NHID + 255) / 256, 256>>>(W1, W2, WL1, WL2, bL1, bL2);
    convert_x_kernel<<<(N_NODES * NFEAT + 255) / 256, 256>>>(x);

    // layer 1
    gemm_mma_kernel<false><<<dim3(2, MTILES), 256, GEMM_SMEM>>>(xh, xl, w1h, w1l, S, N_NODES, NHID);
    spmm_half_kernel<<<spmm_blocks, 256>>>(S, es, ew, b1, hh, hl, 0);
    spmm_half_kernel<<<spmm_blocks, 256>>>(S, es, ew, b1, hh, hl, 128);
    // layer 2
    gemm_mma_kernel<false><<<dim3(2, MTILES), 256, GEMM_SMEM>>>(hh, hl, w2h, w2l, S, N_NODES, NHID);
    spmm_half_kernel<<<spmm_blocks, 256>>>(S, es, ew, b2, hh, hl, 0);
    spmm_half_kernel<<<spmm_blocks, 256>>>(S, es, ew, b2, hh, hl, 128);
    // twin heads
    gemm_mma_kernel<true><<<dim3(1, MTILES), 256, GEMM_SMEM>>>(hh, hl, whh, whl, (float*)d_out, N_NODES, 128);
}